// round 1
// baseline (speedup 1.0000x reference)
#include <cuda_runtime.h>

// DeformConv3d: B=2, Cin=32, Cout=64, D=8, H=W=48, 3x3x3, stride1, pad1, dil1,
// groups=1, DG=1. Offsets only on (h,w); d is rigid per-tap.

#define CIN   32
#define COUT  64
#define DDIM  8
#define HDIM  48
#define WDIM  48
#define KTAPS 27
#define POS   32                 // output positions per block
#define PLANE (HDIM * WDIM)      // 2304
#define SPATIAL (DDIM * PLANE)   // 18432
#define BATCH 2

// Pre-transposed weight: wT[k][cin][co]
__device__ float g_wT[KTAPS * CIN * COUT];

__global__ void transpose_w_kernel(const float* __restrict__ w) {
    int i = blockIdx.x * blockDim.x + threadIdx.x;
    if (i >= KTAPS * CIN * COUT) return;
    int k   = i / (CIN * COUT);
    int r   = i - k * (CIN * COUT);
    int cin = r / COUT;
    int co  = r - cin * COUT;
    // weight layout: [Cout][Cin][K]
    g_wT[i] = w[co * (CIN * KTAPS) + cin * KTAPS + k];
}

__global__ __launch_bounds__(256) void dcn3d_kernel(
    const float* __restrict__ x,
    const float* __restrict__ offs,
    const float* __restrict__ mask,
    const float* __restrict__ bias,
    float* __restrict__ out)
{
    __shared__ float s_val[CIN][POS];     // sampled values, [cin][pos]
    __shared__ float s_w[CIN * COUT];     // tap weights, [cin][co]

    const int t    = threadIdx.x;
    const int lane = t & 31;
    const int g    = t >> 5;              // warp id 0..7

    // Global output position for this lane
    const int P    = blockIdx.x * POS + lane;
    const int b    = P / SPATIAL;
    const int sp   = P - b * SPATIAL;     // spatial index within batch
    const int dout = sp / PLANE;
    const int r2   = sp - dout * PLANE;
    const int ho   = r2 / WDIM;
    const int wo   = r2 - ho * WDIM;

    const float* xb   = x    + b * (CIN * SPATIAL);
    const float* offb = offs + b * (2 * KTAPS * SPATIAL) + sp;
    const float* mb   = mask + b * (KTAPS * SPATIAL) + sp;

    float acc[8];
    #pragma unroll
    for (int j = 0; j < 8; j++) acc[j] = 0.f;

    for (int k = 0; k < KTAPS; k++) {
        const int kd = k / 9;
        const int kh = (k - kd * 9) / 3;
        const int kw = k - kd * 9 - kh * 3;

        __syncthreads();  // previous tap's GEMM reads done before overwrite

        // stage weight slice [cin][co] for tap k (coalesced, 8 floats/thread)
        #pragma unroll
        for (int j = 0; j < 8; j++) {
            int idx = t * 8 + j;
            s_w[idx] = g_wT[k * (CIN * COUT) + idx];
        }

        // --- sampling: warp g covers channels [4g, 4g+4) at position 'lane' ---
        const float oh = offb[(2 * k)     * SPATIAL];
        const float ow = offb[(2 * k + 1) * SPATIAL];
        const float m  = mb[k * SPATIAL];

        const int  dp  = kd + dout - 1;
        const bool vdd = (dp >= 0) && (dp < DDIM);
        const int  di  = min(max(dp, 0), DDIM - 1);

        const float h = (float)(kh + ho - 1) + oh;
        const float w = (float)(kw + wo - 1) + ow;
        const float h0f = floorf(h), w0f = floorf(w);
        const float lh = h - h0f, lw = w - w0f;
        const int h0 = (int)h0f, w0 = (int)w0f;
        const int h1 = h0 + 1,   w1 = w0 + 1;

        const bool bh0 = (h0 >= 0) && (h0 < HDIM);
        const bool bh1 = (h1 >= 0) && (h1 < HDIM);
        const bool bw0 = (w0 >= 0) && (w0 < WDIM);
        const bool bw1 = (w1 >= 0) && (w1 < WDIM);

        const float w00 = (1.f - lh) * (1.f - lw) * ((bh0 && bw0 && vdd) ? m : 0.f);
        const float w01 = (1.f - lh) * lw         * ((bh0 && bw1 && vdd) ? m : 0.f);
        const float w10 = lh * (1.f - lw)         * ((bh1 && bw0 && vdd) ? m : 0.f);
        const float w11 = lh * lw                 * ((bh1 && bw1 && vdd) ? m : 0.f);

        const int hc0 = min(max(h0, 0), HDIM - 1);
        const int hc1 = min(max(h1, 0), HDIM - 1);
        const int wc0 = min(max(w0, 0), WDIM - 1);
        const int wc1 = min(max(w1, 0), WDIM - 1);

        const int i00 = hc0 * WDIM + wc0;
        const int i01 = hc0 * WDIM + wc1;
        const int i10 = hc1 * WDIM + wc0;
        const int i11 = hc1 * WDIM + wc1;

        const float* xp = xb + (g * 4) * SPATIAL + di * PLANE;
        #pragma unroll
        for (int c = 0; c < 4; c++) {
            const float* p = xp + c * SPATIAL;
            float v = w00 * p[i00] + w01 * p[i01] + w10 * p[i10] + w11 * p[i11];
            s_val[g * 4 + c][lane] = v;
        }

        __syncthreads();

        // --- GEMM accumulate: thread (g,lane) -> co in [8g, 8g+8), pos = lane ---
        #pragma unroll
        for (int cin = 0; cin < CIN; cin++) {
            const float sv = s_val[cin][lane];
            const float4 wa = *(const float4*)&s_w[cin * COUT + g * 8];
            const float4 wb = *(const float4*)&s_w[cin * COUT + g * 8 + 4];
            acc[0] += wa.x * sv;  acc[1] += wa.y * sv;
            acc[2] += wa.z * sv;  acc[3] += wa.w * sv;
            acc[4] += wb.x * sv;  acc[5] += wb.y * sv;
            acc[6] += wb.z * sv;  acc[7] += wb.w * sv;
        }
    }

    // write output: out[b][co][sp]
    const int obase = b * (COUT * SPATIAL) + sp;
    #pragma unroll
    for (int j = 0; j < 8; j++) {
        const int co = g * 8 + j;
        out[obase + co * SPATIAL] = acc[j] + __ldg(&bias[co]);
    }
}

extern "C" void kernel_launch(void* const* d_in, const int* in_sizes, int n_in,
                              void* d_out, int out_size)
{
    const float* x    = (const float*)d_in[0];
    const float* offs = (const float*)d_in[1];
    const float* mask = (const float*)d_in[2];
    const float* w    = (const float*)d_in[3];
    const float* bias = (const float*)d_in[4];
    float* out = (float*)d_out;

    transpose_w_kernel<<<(KTAPS * CIN * COUT + 255) / 256, 256>>>(w);

    const int nblocks = (BATCH * SPATIAL) / POS;  // 36864/32 = 1152
    dcn3d_kernel<<<nblocks, 256>>>(x, offs, mask, bias, out);
}

// round 2
// speedup vs baseline: 1.6673x; 1.6673x over previous
#include <cuda_runtime.h>

typedef unsigned long long u64;

// DeformConv3d: B=2, Cin=32, Cout=64, D=8, H=W=48, 3x3x3, stride1, pad1, dil1.
#define CIN   32
#define COUT  64
#define DDIM  8
#define HDIM  48
#define WDIM  48
#define KTAPS 27
#define POS   64                 // output positions per block
#define THREADS 128
#define PLANE (HDIM * WDIM)      // 2304
#define SPATIAL (DDIM * PLANE)   // 18432
#define BATCH 2

// Pre-transposed + co-permuted weight: g_wT[k][cin][slot], where
// slot = (j>>2)*32 + ct*4 + (j&3) for co = ct*8 + j.  This makes both
// per-thread weight LDS.128 bank-conflict-free (word stride 4).
__device__ float g_wT[KTAPS * CIN * COUT];

__global__ void prep_w_kernel(const float* __restrict__ w) {
    int i = blockIdx.x * blockDim.x + threadIdx.x;
    if (i >= KTAPS * CIN * COUT) return;
    int k   = i / (CIN * COUT);
    int r   = i - k * (CIN * COUT);
    int cin = r >> 6;            // /64
    int co  = r & 63;
    int ct  = co >> 3;
    int j   = co & 7;
    int slot = (j >> 2) * 32 + ct * 4 + (j & 3);
    // weight layout: [Cout][Cin][K]
    g_wT[k * (CIN * COUT) + cin * COUT + slot] =
        w[co * (CIN * KTAPS) + cin * KTAPS + k];
}

__device__ __forceinline__ u64 dup_f32x2(float v) {
    u64 r;
    asm("mov.b64 %0, {%1, %1};" : "=l"(r) : "f"(v));
    return r;
}

__global__ __launch_bounds__(THREADS) void dcn3d_kernel(
    const float* __restrict__ x,
    const float* __restrict__ offs,
    const float* __restrict__ mask,
    const float* __restrict__ bias,
    float* __restrict__ out)
{
    __shared__ float s_val[CIN * POS];   // [cin][pos]
    __shared__ float s_w[CIN * COUT];    // [cin][slot]

    const int t  = threadIdx.x;

    // GEMM mapping: thread -> (pos tile of 4, co tile of 8)
    const int ct = t & 7;                // co block: co = ct*8 + j
    const int pt = t >> 3;               // pos block: pos = pt*4 + p  (0..15)

    // Sampling mapping: thread -> (position, channel group of 16)
    const int posl = t & 63;
    const int cgrp = t >> 6;             // 0..1

    const int P    = blockIdx.x * POS + posl;
    const int b    = P / SPATIAL;
    const int sp   = P - b * SPATIAL;
    const int dout = sp / PLANE;
    const int r2   = sp - dout * PLANE;
    const int ho   = r2 / WDIM;
    const int wo   = r2 - ho * WDIM;

    const float* xb   = x    + b * (CIN * SPATIAL);
    const float* offb = offs + b * (2 * KTAPS * SPATIAL) + sp;
    const float* mb   = mask + b * (KTAPS * SPATIAL) + sp;

    u64 acc[8][2];                       // [co j][pos-pair]; f32x2 packed
    #pragma unroll
    for (int j = 0; j < 8; j++) { acc[j][0] = 0ULL; acc[j][1] = 0ULL; }

    for (int k = 0; k < KTAPS; k++) {
        const int kd = k / 9;
        const int kh = (k - kd * 9) / 3;
        const int kw = k - kd * 9 - kh * 3;

        __syncthreads();   // previous tap's GEMM reads complete

        // stage tap-k weight slice: 2048 floats, 16 per thread (coalesced)
        {
            const float4* src = (const float4*)(g_wT + k * (CIN * COUT)) + t * 4;
            float4* dst = (float4*)s_w + t * 4;
            dst[0] = src[0]; dst[1] = src[1]; dst[2] = src[2]; dst[3] = src[3];
        }

        // --- sampling: this thread covers channels [cgrp*16, cgrp*16+16) at 'posl' ---
        const float oh = offb[(2 * k)     * SPATIAL];
        const float ow = offb[(2 * k + 1) * SPATIAL];
        const float m  = mb[k * SPATIAL];

        const int  dp  = kd + dout - 1;
        const bool vdd = (dp >= 0) && (dp < DDIM);
        const int  di  = min(max(dp, 0), DDIM - 1);

        const float h = (float)(kh + ho - 1) + oh;
        const float w = (float)(kw + wo - 1) + ow;
        const float h0f = floorf(h), w0f = floorf(w);
        const float lh = h - h0f, lw = w - w0f;
        const int h0 = (int)h0f, w0 = (int)w0f;
        const int h1 = h0 + 1,   w1 = w0 + 1;

        const bool bh0 = (h0 >= 0) && (h0 < HDIM);
        const bool bh1 = (h1 >= 0) && (h1 < HDIM);
        const bool bw0 = (w0 >= 0) && (w0 < WDIM);
        const bool bw1 = (w1 >= 0) && (w1 < WDIM);

        const float w00 = (1.f - lh) * (1.f - lw) * ((bh0 && bw0 && vdd) ? m : 0.f);
        const float w01 = (1.f - lh) * lw         * ((bh0 && bw1 && vdd) ? m : 0.f);
        const float w10 = lh * (1.f - lw)         * ((bh1 && bw0 && vdd) ? m : 0.f);
        const float w11 = lh * lw                 * ((bh1 && bw1 && vdd) ? m : 0.f);

        const int hc0 = min(max(h0, 0), HDIM - 1);
        const int hc1 = min(max(h1, 0), HDIM - 1);
        const int wc0 = min(max(w0, 0), WDIM - 1);
        const int wc1 = min(max(w1, 0), WDIM - 1);

        const int i00 = hc0 * WDIM + wc0;
        const int i01 = hc0 * WDIM + wc1;
        const int i10 = hc1 * WDIM + wc0;
        const int i11 = hc1 * WDIM + wc1;

        const float* xp = xb + (cgrp * 16) * SPATIAL + di * PLANE;
        #pragma unroll
        for (int c = 0; c < 16; c++) {
            const float* p = xp + c * SPATIAL;
            float v = w00 * p[i00] + w01 * p[i01] + w10 * p[i10] + w11 * p[i11];
            s_val[(cgrp * 16 + c) * POS + posl] = v;
        }

        __syncthreads();

        // --- GEMM: acc[j][pp] += sval_pair[pp] * dup(w[co=ct*8+j]) ---
        #pragma unroll
        for (int cin = 0; cin < CIN; cin++) {
            const float4 svq = *(const float4*)(s_val + cin * POS + pt * 4);
            const u64 sv01 = ((const u64*)&svq)[0];   // (pos0, pos1)
            const u64 sv23 = ((const u64*)&svq)[1];   // (pos2, pos3)
            const float4 wqa = *(const float4*)(s_w + cin * COUT + ct * 4);
            const float4 wqb = *(const float4*)(s_w + cin * COUT + 32 + ct * 4);
            const float wj[8] = {wqa.x, wqa.y, wqa.z, wqa.w,
                                 wqb.x, wqb.y, wqb.z, wqb.w};
            #pragma unroll
            for (int j = 0; j < 8; j++) {
                const u64 wd = dup_f32x2(wj[j]);
                asm("fma.rn.f32x2 %0, %1, %2, %0;"
                    : "+l"(acc[j][0]) : "l"(sv01), "l"(wd));
                asm("fma.rn.f32x2 %0, %1, %2, %0;"
                    : "+l"(acc[j][1]) : "l"(sv23), "l"(wd));
            }
        }
    }

    // epilogue: thread owns pos [P0, P0+4) x co [ct*8, ct*8+8)
    const int P0  = blockIdx.x * POS + pt * 4;
    const int b0  = P0 / SPATIAL;
    const int sp0 = P0 - b0 * SPATIAL;
    float* ob = out + b0 * (COUT * SPATIAL) + sp0;
    #pragma unroll
    for (int j = 0; j < 8; j++) {
        const int co = ct * 8 + j;
        const float bv = __ldg(&bias[co]);
        float f0, f1, f2, f3;
        asm("mov.b64 {%0, %1}, %2;" : "=f"(f0), "=f"(f1) : "l"(acc[j][0]));
        asm("mov.b64 {%0, %1}, %2;" : "=f"(f2), "=f"(f3) : "l"(acc[j][1]));
        float4 o;
        o.x = f0 + bv; o.y = f1 + bv; o.z = f2 + bv; o.w = f3 + bv;
        *(float4*)(ob + co * SPATIAL) = o;
    }
}

extern "C" void kernel_launch(void* const* d_in, const int* in_sizes, int n_in,
                              void* d_out, int out_size)
{
    const float* x    = (const float*)d_in[0];
    const float* offs = (const float*)d_in[1];
    const float* mask = (const float*)d_in[2];
    const float* w    = (const float*)d_in[3];
    const float* bias = (const float*)d_in[4];
    float* out = (float*)d_out;

    prep_w_kernel<<<(KTAPS * CIN * COUT + 255) / 256, 256>>>(w);

    const int nblocks = (BATCH * SPATIAL) / POS;   // 576
    dcn3d_kernel<<<nblocks, THREADS>>>(x, offs, mask, bias, out);
}